// round 3
// baseline (speedup 1.0000x reference)
#include <cuda_runtime.h>
#include <cuda_bf16.h>
#include <stdint.h>

#define BUCKET_SIZE 512
#define G 296          // tile-blocks for pass1/pass3 (2 per SM)
#define BLK1 256       // 8 warps -> one 6-bit field per warp in a u64
#define BLK3 512
#define MAXNB 8192     // actual nb = 7813
#define MAXN  4194304  // actual n = 4,000,000

// per-(block,bucket) histogram -> exclusive block offsets (L2-resident, 9.7MB)
__device__ int g_hist[(size_t)G * MAXNB];
// per-point packed (bucket << 10 | local_rank) scratch
__device__ unsigned g_word[MAXN];

// ------- Pass 1: bucket + per-block STABLE local rank + histogram -------
__global__ __launch_bounds__(BLK1) void psh_pass1(
    const float* __restrict__ coords, const int* __restrict__ seps,
    const int* __restrict__ hop_p, int n, int nB, int nb,
    unsigned long long magic, float* __restrict__ out_bucket,
    unsigned* __restrict__ words)
{
    extern __shared__ int sh[];
    unsigned long long* packed = (unsigned long long*)sh;  // [nb]
    int* off = (int*)(packed + nb);                        // [nb] running counts
    for (int j = threadIdx.x; j < nb; j += BLK1) { packed[j] = 0ull; off[j] = 0; }
    __syncthreads();

    const unsigned hop = (unsigned)hop_p[0];
    const int tile = (n + G - 1) / G;
    const int beg = blockIdx.x * tile;
    const int end = min(n, beg + tile);
    const int lane   = threadIdx.x & 31;
    const int warpid = threadIdx.x >> 5;

    // bid(i) = #{k : seps[k] <= i}; only seps inside (beg, end-1] vary.
    int klo = 0, khi = 0;
    for (int k = 0; k < nB; k++) {
        int s = __ldg(&seps[k]);
        klo += (s <= beg);
        khi += (s <= end - 1);
    }

    int i = beg + threadIdx.x;
    bool vcur = (i < end);
    float x = 0.f, y = 0.f, z = 0.f;
    if (vcur) { x = coords[3*i]; y = coords[3*i+1]; z = coords[3*i+2]; }

    for (int c = beg; c < end; c += BLK1) {
        // prefetch next chunk BEFORE the barrier section (hide DRAM latency)
        int ni = i + BLK1;
        bool vnext = (ni < end);
        float nx = 0.f, ny = 0.f, nz = 0.f;
        if (vnext) { nx = coords[3*ni]; ny = coords[3*ni+1]; nz = coords[3*ni+2]; }

        unsigned vm = __ballot_sync(0xffffffffu, vcur);
        unsigned b = 0, mask = 0;
        int leader = 0, intra = 0, cnt = 0;
        if (vcur) {
            unsigned bid = (unsigned)klo;
            for (int k = klo; k < khi; k++) bid += (__ldg(&seps[k]) <= i);
            unsigned vx = (unsigned)(int)floorf(x);
            unsigned vy = (unsigned)(int)floorf(y);
            unsigned vz = (unsigned)(int)floorf(z);
            unsigned h = vx * 73856093u ^ vy * 19349663u ^ vz * 83492791u
                       ^ bid * 2654435761u;
            h += hop;
            unsigned q = (unsigned)__umul64hi((unsigned long long)h, magic);
            b = h - q * (unsigned)nb;
            mask   = __match_any_sync(vm, b);
            leader = __ffs(mask) - 1;
            intra  = __popc(mask & ((1u << lane) - 1u));
            cnt    = __popc(mask);  // <= 32, fits 6 bits
        }
        bool isLeader = vcur && (lane == leader);

        if (isLeader)
            atomicAdd(&packed[b], (unsigned long long)cnt << (6 * warpid));
        __syncthreads();

        int bp = 0, total = 0, loww = 8;
        if (isLeader) {
            unsigned long long word = packed[b];
            int prefix = 0;
            #pragma unroll
            for (int w = 0; w < 8; w++) {
                int f = (int)((word >> (6 * w)) & 63u);
                total += f;
                if (w < warpid) prefix += f;
                if (f && loww == 8) loww = w;
            }
            bp = off[b] + prefix;  // stable base for this warp's group
        }
        __syncthreads();
        if (isLeader && warpid == loww) {
            off[b] = bp + total;   // owner has prefix==0
            packed[b] = 0ull;
        }

        if (vcur) {
            int lr = __shfl_sync(mask, bp, leader) + intra;
            lr = min(lr, BUCKET_SIZE);              // >=512 -> dropped anyway
            words[i] = (b << 10) | (unsigned)lr;    // b:13b | lr:10b
            out_bucket[i] = (float)b;
        }
        __syncthreads();  // packed[] zeroing visible before next chunk's adds

        i = ni; vcur = vnext; x = nx; y = ny; z = nz;
    }
    __syncthreads();
    for (int j = threadIdx.x; j < nb; j += BLK1)
        g_hist[(size_t)blockIdx.x * nb + j] = off[j];
}

// ------- Pass 2: lane-per-bucket exclusive scan (coalesced) + counts + deficit fill -------
__global__ __launch_bounds__(64) void psh_pass2(
    int nb, float* __restrict__ out_counts, float* __restrict__ out_coord)
{
    int j = blockIdx.x * 64 + threadIdx.x;
    if (j >= nb) return;
    int carry = 0;
    #pragma unroll 8
    for (int r = 0; r < G; r++) {
        size_t idx = (size_t)r * nb + j;
        int v = g_hist[idx];
        g_hist[idx] = carry;
        carry += v;
    }
    out_counts[j] = (float)carry;
    int filled = min(carry, BUCKET_SIZE);
    float* dst = out_coord + ((size_t)j * BUCKET_SIZE + filled) * 3;
    int nz = (BUCKET_SIZE - filled) * 3;
    for (int t = 0; t < nz; t++) dst[t] = 0.0f;
}

// ------- Pass 3: barrier-free streaming scatter -------
__global__ __launch_bounds__(BLK3) void psh_pass3(
    const float* __restrict__ coords, const unsigned* __restrict__ words,
    int n, int nb, float* __restrict__ out_coord)
{
    extern __shared__ int off[];
    for (int j = threadIdx.x; j < nb; j += BLK3)
        off[j] = g_hist[(size_t)blockIdx.x * nb + j];
    __syncthreads();

    const int tile = (n + G - 1) / G;
    const int beg = blockIdx.x * tile;
    const int end = min(n, beg + tile);

    for (int i = beg + threadIdx.x; i < end; i += BLK3) {
        unsigned w = words[i];
        float x = coords[3*i], y = coords[3*i+1], z = coords[3*i+2];
        unsigned b = w >> 10;
        int rank = off[b] + (int)(w & 1023u);
        if (rank < BUCKET_SIZE) {
            size_t s = ((size_t)b * BUCKET_SIZE + rank) * 3;
            out_coord[s + 0] = x;
            out_coord[s + 1] = y;
            out_coord[s + 2] = z;
        }
    }
}

extern "C" void kernel_launch(void* const* d_in, const int* in_sizes, int n_in,
                              void* d_out, int out_size)
{
    const float* coords = (const float*)d_in[0];
    const int*   seps   = (const int*)d_in[1];
    const int*   hop_p  = (const int*)d_in[2];

    const int n  = in_sizes[0] / 3;
    const int nB = in_sizes[1];
    const int pad_to = ((n + BUCKET_SIZE - 1) / BUCKET_SIZE) * BUCKET_SIZE;
    const int nb = pad_to / BUCKET_SIZE;

    float* out_coord  = (float*)d_out;
    float* out_counts = out_coord + (size_t)pad_to * 3;
    float* out_bucket = out_counts + nb;

    unsigned long long magic = (~0ULL) / (unsigned)nb + 1ULL;

    unsigned* words = nullptr;
    cudaGetSymbolAddress((void**)&words, g_word);

    size_t sh1 = (size_t)nb * 12 + 16;   // u64 packed + int off
    size_t sh3 = (size_t)nb * sizeof(int);

    static bool attr_set = false;
    if (!attr_set) {
        cudaFuncSetAttribute(psh_pass1,
                             cudaFuncAttributeMaxDynamicSharedMemorySize,
                             (int)((size_t)MAXNB * 12 + 16));
        attr_set = true;
    }

    psh_pass1<<<G, BLK1, sh1>>>(coords, seps, hop_p, n, nB, nb, magic,
                                out_bucket, words);
    psh_pass2<<<(nb + 63) / 64, 64>>>(nb, out_counts, out_coord);
    psh_pass3<<<G, BLK3, sh3>>>(coords, words, n, nb, out_coord);
}